// round 6
// baseline (speedup 1.0000x reference)
#include <cuda_runtime.h>

#define BATCH 8
#define CH 128
#define HH 128
#define WW 128
#define KW 9
#define PW 4

// fp32 working state in (b, i, j, c) layout. 64 MB static device array
// (allocation-free scratch, per harness rules).
__device__ float g_y[BATCH * HH * WW * CH];

typedef unsigned long long u64;

__device__ __forceinline__ u64 pack2(float x) {
    u64 r;
    asm("mov.b64 %0, {%1, %1};" : "=l"(r) : "f"(x));
    return r;
}
__device__ __forceinline__ void fma2(u64& d, u64 a, u64 b) {
    asm("fma.rn.f32x2 %0, %1, %2, %0;" : "+l"(d) : "l"(a), "l"(b));
}
__device__ __forceinline__ float2 unpack2(u64 v) {
    float2 f;
    asm("mov.b64 {%0, %1}, %2;" : "=f"(f.x), "=f"(f.y) : "l"(v));
    return f;
}

// ---------------------------------------------------------------------------
// Transpose in: x (B,C,H,W) -> g_y (B,H,W,C)
// ---------------------------------------------------------------------------
__global__ void t_in_kernel(const float* __restrict__ x) {
    __shared__ float tile[32][33];
    int b = blockIdx.z >> 7;
    int h = blockIdx.z & 127;
    int w0 = blockIdx.x * 32;
    int c0 = blockIdx.y * 32;
    int tx = threadIdx.x, ty = threadIdx.y;
#pragma unroll
    for (int k = 0; k < 32; k += 8) {
        int c = c0 + ty + k;
        tile[ty + k][tx] = x[(((b * CH + c) * HH + h) * WW) + w0 + tx];
    }
    __syncthreads();
#pragma unroll
    for (int k = 0; k < 32; k += 8) {
        int w = w0 + ty + k;
        g_y[(((b * HH + h) * WW + w) * CH) + c0 + tx] = tile[tx][ty + k];
    }
}

// ---------------------------------------------------------------------------
// Transpose out: g_y (B,H,W,C) -> out (B,C,H,W)
// ---------------------------------------------------------------------------
__global__ void t_out_kernel(float* __restrict__ o) {
    __shared__ float tile[32][33];
    int b = blockIdx.z >> 7;
    int h = blockIdx.z & 127;
    int w0 = blockIdx.x * 32;
    int c0 = blockIdx.y * 32;
    int tx = threadIdx.x, ty = threadIdx.y;
#pragma unroll
    for (int k = 0; k < 32; k += 8) {
        int w = w0 + ty + k;
        tile[ty + k][tx] = g_y[(((b * HH + h) * WW + w) * CH) + c0 + tx];
    }
    __syncthreads();
#pragma unroll
    for (int k = 0; k < 32; k += 8) {
        int c = c0 + ty + k;
        o[(((b * CH + c) * HH + h) * WW) + w0 + tx] = tile[tx][ty + k];
    }
}

// ---------------------------------------------------------------------------
// One scan step (in-place):
//   y[cur][m][co] += relu( sum_{t,ci} y[prev][m+t-4][ci] * K[t][ci][co] )
// stride_m: element stride along the conv axis (128 for H-scan rows,
// 16384 for W-scan columns). cur_off / prev_off: element offsets of the
// current / previous scan position within one batch image.
// Grid: (4 m-tiles, 4 co-tiles, 8 batches), 128 threads.
// Thread computes 2 m-positions x 4 output channels using packed f32x2 FMA.
// ---------------------------------------------------------------------------
__global__ void __launch_bounds__(128) step_kernel(
    const float* __restrict__ Kw, int cur_off, int prev_off, int stride_m) {
    __shared__ float sp[40][132];  // prev rows mt-4 .. mt+35, padded rows

    int tid = threadIdx.x;
    int b = blockIdx.z;
    int mt = blockIdx.x * 32;
    int co0 = blockIdx.y * 32;
    const float* prow = g_y + (size_t)b * (HH * WW * CH) + prev_off;

    // Stage prev rows with halo into SMEM (zero-padded at boundaries).
#pragma unroll
    for (int ch = 0; ch < 10; ch++) {
        int lin = ch * 512 + tid * 4;
        int r = lin >> 7;
        int ci = lin & 127;
        int row = mt - 4 + r;
        float4 v = make_float4(0.f, 0.f, 0.f, 0.f);
        if (row >= 0 && row < HH)
            v = *(const float4*)(prow + (size_t)row * stride_m + ci);
        *(float4*)(&sp[r][ci]) = v;
    }
    __syncthreads();

    int cg = tid & 7;        // co group: 4 channels
    int mp = tid >> 3;       // 0..15
    int m0 = mp, m1 = mp + 16;
    const float* kb = Kw + co0 + cg * 4;

    u64 a00 = 0, a01 = 0, a10 = 0, a11 = 0;

    for (int t = 0; t < KW; t++) {
        const float* kt = kb + t * (CH * CH);
        const float* s0 = &sp[m0 + t][0];
        const float* s1 = &sp[m1 + t][0];
#pragma unroll 4
        for (int ci = 0; ci < CH; ci++) {
            u64 p0 = pack2(s0[ci]);
            u64 p1 = pack2(s1[ci]);
            ulonglong2 w = *(const ulonglong2*)(kt + ci * CH);
            fma2(a00, p0, w.x);
            fma2(a01, p0, w.y);
            fma2(a10, p1, w.x);
            fma2(a11, p1, w.y);
        }
    }

    float* crow = g_y + (size_t)b * (HH * WW * CH) + cur_off;
    float2 r00 = unpack2(a00), r01 = unpack2(a01);
    float2 r10 = unpack2(a10), r11 = unpack2(a11);

    {
        float4* o0 = (float4*)(crow + (size_t)(mt + m0) * stride_m + co0 + cg * 4);
        float4 c = *o0;
        c.x += fmaxf(r00.x, 0.f);
        c.y += fmaxf(r00.y, 0.f);
        c.z += fmaxf(r01.x, 0.f);
        c.w += fmaxf(r01.y, 0.f);
        *o0 = c;
    }
    {
        float4* o1 = (float4*)(crow + (size_t)(mt + m1) * stride_m + co0 + cg * 4);
        float4 c = *o1;
        c.x += fmaxf(r10.x, 0.f);
        c.y += fmaxf(r10.y, 0.f);
        c.z += fmaxf(r11.x, 0.f);
        c.w += fmaxf(r11.y, 0.f);
        *o1 = c;
    }
}

// ---------------------------------------------------------------------------
extern "C" void kernel_launch(void* const* d_in, const int* in_sizes, int n_in,
                              void* d_out, int out_size) {
    const float* x   = (const float*)d_in[0];
    const float* ktd = (const float*)d_in[1];
    const float* kdt = (const float*)d_in[2];
    const float* klr = (const float*)d_in[3];
    const float* krl = (const float*)d_in[4];

    dim3 tb(32, 8);
    dim3 tg(WW / 32, CH / 32, BATCH * HH);
    t_in_kernel<<<tg, tb>>>(x);

    dim3 sg(4, 4, BATCH);
    const int ROW = WW * CH;  // 16384

    // Top-down: scan i, conv along j (stride_m = CH)
    for (int p = 1; p < HH; p++)
        step_kernel<<<sg, 128>>>(ktd, p * ROW, (p - 1) * ROW, CH);
    // Bottom-up
    for (int p = HH - 2; p >= 0; p--)
        step_kernel<<<sg, 128>>>(kdt, p * ROW, (p + 1) * ROW, CH);
    // Left-right: scan j, conv along i (stride_m = W*C)
    for (int p = 1; p < WW; p++)
        step_kernel<<<sg, 128>>>(klr, p * CH, (p - 1) * CH, ROW);
    // Right-left
    for (int p = WW - 2; p >= 0; p--)
        step_kernel<<<sg, 128>>>(krl, p * CH, (p + 1) * CH, ROW);

    t_out_kernel<<<tg, tb>>>((float*)d_out);
}

// round 10
// speedup vs baseline: 4.7913x; 4.7913x over previous
#include <cuda_runtime.h>

#define BATCH 8
#define CH 128
#define HH 128
#define WW 128
#define KW 9
#define HWC (HH * WW * CH)
#define NCTA 128
#define AROW 130            // u64 row stride in SMEM (padded: conflict-free)
#define SMEM_BYTES (2 * 72 * AROW * 8)   // w_s + a_s = 149760 B

// fp32 working state in (b, i, j, c) layout. 64 MB static device scratch.
__device__ float g_y[BATCH * HH * WW * CH];
// grid-barrier state; protocol restores all of it to 0 before kernel exit,
// so every launch (and every graph replay) starts from zeros.
__device__ int g_bars[128];
__device__ int g_done;

typedef unsigned long long u64;

__device__ __forceinline__ u64 pack2(float x) {
    u64 r;
    asm("mov.b64 %0, {%1, %1};" : "=l"(r) : "f"(x));
    return r;
}
__device__ __forceinline__ u64 packf2(float x, float y) {
    u64 r;
    asm("mov.b64 %0, {%1, %2};" : "=l"(r) : "f"(x), "f"(y));
    return r;
}
__device__ __forceinline__ void fma2(u64& d, u64 a, u64 b) {
    asm("fma.rn.f32x2 %0, %1, %2, %0;" : "+l"(d) : "l"(a), "l"(b));
}
__device__ __forceinline__ float2 unpack2(u64 v) {
    float2 f;
    asm("mov.b64 {%0, %1}, %2;" : "=f"(f.x), "=f"(f.y) : "l"(v));
    return f;
}

// ---------------------------------------------------------------------------
// Grid barrier (all 128 CTAs co-resident: 1 CTA/SM via SMEM, grid=128<=148).
// Slot s is zeroed by CTA0 after barrier s+1 completes (provably dead then).
// ---------------------------------------------------------------------------
__device__ __forceinline__ void grid_barrier(int s) {
    __threadfence();          // release all this CTA's global stores
    __syncthreads();
    if (threadIdx.x == 0) {
        atomicAdd(&g_bars[s], 1);
        while (*(volatile int*)&g_bars[s] < NCTA) { }
        __threadfence();      // acquire
    }
    __syncthreads();
    if (blockIdx.x == 0 && threadIdx.x == 0 && s > 0) g_bars[s - 1] = 0;
}

// ---------------------------------------------------------------------------
// Transpose in: x (B,C,H,W) -> g_y (B,H,W,C)
// ---------------------------------------------------------------------------
__global__ void t_in_kernel(const float* __restrict__ x) {
    __shared__ float tile[32][33];
    int b = blockIdx.z >> 7;
    int h = blockIdx.z & 127;
    int w0 = blockIdx.x * 32;
    int c0 = blockIdx.y * 32;
    int tx = threadIdx.x, ty = threadIdx.y;
#pragma unroll
    for (int k = 0; k < 32; k += 8) {
        int c = c0 + ty + k;
        tile[ty + k][tx] = x[(((b * CH + c) * HH + h) * WW) + w0 + tx];
    }
    __syncthreads();
#pragma unroll
    for (int k = 0; k < 32; k += 8) {
        int w = w0 + ty + k;
        g_y[(((b * HH + h) * WW + w) * CH) + c0 + tx] = tile[tx][ty + k];
    }
}

// ---------------------------------------------------------------------------
// Transpose out: g_y (B,H,W,C) -> out (B,C,H,W)
// ---------------------------------------------------------------------------
__global__ void t_out_kernel(float* __restrict__ o) {
    __shared__ float tile[32][33];
    int b = blockIdx.z >> 7;
    int h = blockIdx.z & 127;
    int w0 = blockIdx.x * 32;
    int c0 = blockIdx.y * 32;
    int tx = threadIdx.x, ty = threadIdx.y;
#pragma unroll
    for (int k = 0; k < 32; k += 8) {
        int w = w0 + ty + k;
        tile[ty + k][tx] = g_y[(((b * HH + h) * WW + w) * CH) + c0 + tx];
    }
    __syncthreads();
#pragma unroll
    for (int k = 0; k < 32; k += 8) {
        int c = c0 + ty + k;
        o[(((b * CH + c) * HH + h) * WW) + w0 + tx] = tile[tx][ty + k];
    }
}

// ---------------------------------------------------------------------------
// Persistent per-direction scan kernel. 127 steps with in-kernel grid sync.
// CTA (cox, b, mh): co tile = 16 channels [cox*16, +16), batch b,
// m half = 64 positions [mh*64, +64) along the conv axis.
// Weights for the co tile live in SMEM for the entire direction, packed as
// f32x2 co-pairs: w_s[(t*8+cop)*AROW + ci].
// Per step, prev scan-line staged into SMEM duplicated: a_s[r*AROW+ci] =
// (v,v), r = conv-pos - (mstart-4), 72 rows incl. halo.
// Thread (cop=tid&7, mg=tid>>3) computes m = mstart + mg + {0,16,32,48},
// co pair co0+2*cop. Hot loop per 2 ci: 5x LDS.128 + 8x FFMA2.
// ---------------------------------------------------------------------------
__global__ void __launch_bounds__(128, 1) scan_kernel(
    const float* __restrict__ Kw, int first, int dir, int stride_p, int stride_m) {
    extern __shared__ u64 sm[];
    u64* w_s = sm;                 // 72*AROW u64
    u64* a_s = sm + 72 * AROW;     // 72*AROW u64

    const int tid = threadIdx.x;
    const int bx = blockIdx.x;
    const int cox = bx & 7;
    const int b = (bx >> 3) & 7;
    const int mh = bx >> 6;
    const int co0 = cox * 16;
    const int mstart = mh * 64;
    const int cop = tid & 7;   // co pair 0..7
    const int mg = tid >> 3;   // 0..15

    // Stage weights once per direction: pack co pairs into u64.
    for (int idx = tid; idx < KW * 8 * CH; idx += 128) {
        int t = idx >> 10;
        int rem = idx & 1023;
        int cp = rem >> 7;
        int ci = rem & 127;
        float2 wv = *(const float2*)(Kw + (size_t)(t * CH + ci) * CH + co0 + 2 * cp);
        w_s[(t * 8 + cp) * AROW + ci] = packf2(wv.x, wv.y);
    }
    __syncthreads();

    float* ybase = g_y + (size_t)b * HWC;

    for (int s = 0; s < 127; ++s) {
        int cur = first + dir * s;
        int prev = cur - dir;

        // Stage prev line (72 conv-positions incl. halo, duplicated f32x2).
        const float* pb = ybase + (size_t)prev * stride_p;
        for (int j = tid; j < 72 * 64; j += 128) {
            int r = j >> 6;       // 0..71
            int c = j & 63;       // float2 chunk; ci = 2c
            int pos = mstart - 4 + r;
            float2 v = make_float2(0.f, 0.f);
            if (pos >= 0 && pos < 128)
                v = *(const float2*)(pb + (size_t)pos * stride_m + 2 * c);
            ulonglong2 d;
            d.x = pack2(v.x);
            d.y = pack2(v.y);
            *(ulonglong2*)(a_s + r * AROW + 2 * c) = d;
        }
        __syncthreads();

        u64 acc0 = 0, acc1 = 0, acc2 = 0, acc3 = 0;
        for (int t = 0; t < KW; ++t) {
            const u64* wr = w_s + (t * 8 + cop) * AROW;
            const u64* ar = a_s + (mg + t) * AROW;
#pragma unroll 8
            for (int ci = 0; ci < CH; ci += 2) {
                ulonglong2 wv = *(const ulonglong2*)(wr + ci);
                ulonglong2 v0 = *(const ulonglong2*)(ar + ci);
                ulonglong2 v1 = *(const ulonglong2*)(ar + 16 * AROW + ci);
                ulonglong2 v2 = *(const ulonglong2*)(ar + 32 * AROW + ci);
                ulonglong2 v3 = *(const ulonglong2*)(ar + 48 * AROW + ci);
                fma2(acc0, v0.x, wv.x);
                fma2(acc1, v1.x, wv.x);
                fma2(acc2, v2.x, wv.x);
                fma2(acc3, v3.x, wv.x);
                fma2(acc0, v0.y, wv.y);
                fma2(acc1, v1.y, wv.y);
                fma2(acc2, v2.y, wv.y);
                fma2(acc3, v3.y, wv.y);
            }
        }

        // RMW output: cur line += relu(acc)
        float* cb = ybase + (size_t)cur * stride_p;
        int co = co0 + cop * 2;
        u64 accs[4] = {acc0, acc1, acc2, acc3};
#pragma unroll
        for (int k = 0; k < 4; ++k) {
            int m = mstart + mg + 16 * k;
            float2* op = (float2*)(cb + (size_t)m * stride_m + co);
            float2 old = *op;
            float2 rr = unpack2(accs[k]);
            old.x += fmaxf(rr.x, 0.f);
            old.y += fmaxf(rr.y, 0.f);
            *op = old;
        }

        if (s < 126) grid_barrier(s);
    }

    // End protocol: last CTA to finish resets remaining barrier state so the
    // next launch / graph replay starts from zeros. Safe: a CTA arrives at
    // g_done only after it has fully passed barrier slot 125.
    __threadfence();
    __syncthreads();
    if (threadIdx.x == 0) {
        atomicAdd(&g_done, 1);
        if (blockIdx.x == 0) {
            while (*(volatile int*)&g_done < NCTA) { }
            g_bars[125] = 0;
            __threadfence();
            g_done = 0;
            __threadfence();
        }
    }
}

// ---------------------------------------------------------------------------
extern "C" void kernel_launch(void* const* d_in, const int* in_sizes, int n_in,
                              void* d_out, int out_size) {
    const float* x   = (const float*)d_in[0];
    const float* ktd = (const float*)d_in[1];
    const float* kdt = (const float*)d_in[2];
    const float* klr = (const float*)d_in[3];
    const float* krl = (const float*)d_in[4];

    cudaFuncSetAttribute(scan_kernel, cudaFuncAttributeMaxDynamicSharedMemorySize,
                         SMEM_BYTES);

    dim3 tb(32, 8);
    dim3 tg(WW / 32, CH / 32, BATCH * HH);
    t_in_kernel<<<tg, tb>>>(x);

    const int ROW = WW * CH;  // 16384
    // Top-down: scan i (stride_p=ROW), conv along j (stride_m=CH)
    scan_kernel<<<NCTA, 128, SMEM_BYTES>>>(ktd, 1, 1, ROW, CH);
    // Bottom-up
    scan_kernel<<<NCTA, 128, SMEM_BYTES>>>(kdt, HH - 2, -1, ROW, CH);
    // Left-right: scan j (stride_p=CH), conv along i (stride_m=ROW)
    scan_kernel<<<NCTA, 128, SMEM_BYTES>>>(klr, 1, 1, CH, ROW);
    // Right-left
    scan_kernel<<<NCTA, 128, SMEM_BYTES>>>(krl, WW - 2, -1, CH, ROW);

    t_out_kernel<<<tg, tb>>>((float*)d_out);
}